// round 6
// baseline (speedup 1.0000x reference)
#include <cuda_runtime.h>
#include <math.h>
#include <float.h>

#define MAXN 50000
#define MAXE 800000
#define MAXT (MAXE + MAXN)

// ---------------- scratch (device globals, referenced directly in kernels) ----------------
__device__ int   g_deg[MAXN];
__device__ int   g_off[MAXN + 1];
__device__ int   g_cur[MAXN];
__device__ int   g_srcs[MAXT];
__device__ __align__(16) float g_xl[MAXN * 128];
__device__ __align__(16) float g_xr[MAXN * 128];
__device__ __align__(16) float g_h [MAXN * 128];

// ---------------- packed f32x2 helpers (sm_103a FFMA2 path) ----------------
#define FMA_F32X2(d, a, b, c) \
    asm("fma.rn.f32x2 %0, %1, %2, %3;" : "=l"(d) : "l"(a), "l"(b), "l"(c))
#define PACK_F32X2(out, lo, hi) \
    asm("mov.b64 %0, {%1, %2};" : "=l"(out) : "f"(lo), "f"(hi))
#define UNPACK_F32X2(lo, hi, in) \
    asm("mov.b64 {%0, %1}, %2;" : "=f"(lo), "=f"(hi) : "l"(in))

// ---------------- CSR build ----------------
__global__ void zero_kernel(int n) {
    int i = blockIdx.x * blockDim.x + threadIdx.x;
    if (i < n) g_deg[i] = 0;
}

// edge_index is int32 (JAX x64 disabled)
__global__ void hist_kernel(const int* __restrict__ ei, int E) {
    int e = blockIdx.x * blockDim.x + threadIdx.x;
    if (e < E) atomicAdd(&g_deg[ei[E + e]], 1);
}

__global__ void scan_kernel(int n) {
    __shared__ int sh[1024];
    int t  = threadIdx.x;
    int cs = (n + 1023) >> 10;
    int b  = t * cs;
    int e  = b + cs; if (e > n) e = n; if (e < b) e = b;
    int s = 0;
    for (int i = b; i < e; ++i) s += g_deg[i] + 1;
    sh[t] = s;
    __syncthreads();
    for (int o = 1; o < 1024; o <<= 1) {
        int add = (t >= o) ? sh[t - o] : 0;
        __syncthreads();
        sh[t] += add;
        __syncthreads();
    }
    int run = sh[t] - s;  // exclusive prefix
    for (int i = b; i < e; ++i) {
        g_off[i] = run; g_cur[i] = run;
        run += g_deg[i] + 1;
    }
    if (t == 1023) g_off[n] = run;
}

__global__ void scatter_kernel(const int* __restrict__ ei, int E, int n) {
    int i = blockIdx.x * blockDim.x + threadIdx.x;
    if (i < E) {
        int d = ei[E + i];
        int p = atomicAdd(&g_cur[d], 1);
        g_srcs[p] = ei[i];
    } else if (i < E + n) {
        int v = i - E;               // self loop
        int p = atomicAdd(&g_cur[v], 1);
        g_srcs[p] = v;
    }
}

// ---------------- dual-weight SGEMM (f32x2): Cz[n,M] = A[n,128] @ Wz[128,M] ----------------
// BM=64, BK=16, 256 threads, double-buffered smem, one sync per K-step.
// blockIdx.z selects (W0 -> g_xl) vs (W1 -> g_xr).
// Per thread: 2 row-pairs (4 rows) x TN cols.  BN in {128,64}, TN = BN/16.
#define ASTR 66   // As row stride: even (8B-aligned pairs) + conflict-free STS
template <int BN, int TN>
__global__ __launch_bounds__(256, 3) void sgemm3(const float* __restrict__ Aext, int a_ext,
                                                 const float* __restrict__ W0,
                                                 const float* __restrict__ W1,
                                                 int n, int M) {
    const int K = 128;
    const float* A = a_ext ? Aext : g_h;
    const float* W = (blockIdx.z == 0) ? W0 : W1;
    float*       C = (blockIdx.z == 0) ? g_xl : g_xr;

    __shared__ float As[2][16][ASTR];
    __shared__ float Bs[2][16][BN];

    int t  = threadIdx.x;
    int tx = t & 15;                  // 16 column groups, TN cols each
    int ty = t >> 4;                  // 16 row groups, 4 rows each
    int row0 = blockIdx.y * 64;

    // A-load mapping: 64 rows x 16 k = 256 float4, one per thread
    int aq = t & 3;                   // k-quad
    int ar = t >> 2;                  // row 0..63
    // B-load mapping
    constexpr int QPR = BN / 4;             // float4 per k-row
    constexpr int RPP = 256 / QPR;          // k-rows per pass
    constexpr int BL  = 16 / RPP;           // passes (2 for BN=128, 1 for BN=64)
    int bkr = t / QPR;
    int bcq = t % QPR;

    unsigned long long acc[2][TN];
    #pragma unroll
    for (int i = 0; i < 2; ++i)
        #pragma unroll
        for (int j = 0; j < TN; ++j) acc[i][j] = 0ull;

    // ---- preload tile 0 into buffer 0 ----
    {
        int gr = row0 + ar;
        float4 v = make_float4(0.f, 0.f, 0.f, 0.f);
        if (gr < n) v = *reinterpret_cast<const float4*>(A + (size_t)gr * K + aq * 4);
        As[0][aq * 4 + 0][ar] = v.x; As[0][aq * 4 + 1][ar] = v.y;
        As[0][aq * 4 + 2][ar] = v.z; As[0][aq * 4 + 3][ar] = v.w;
        #pragma unroll
        for (int p = 0; p < BL; ++p)
            *reinterpret_cast<float4*>(&Bs[0][bkr + p * RPP][bcq * 4]) =
                *reinterpret_cast<const float4*>(W + (size_t)(bkr + p * RPP) * M + bcq * 4);
    }
    __syncthreads();

    #pragma unroll
    for (int it = 0; it < 8; ++it) {
        int cb = it & 1;
        // prefetch next tile into registers
        float4 av;
        float4 bv[BL];
        if (it < 7) {
            int k0 = (it + 1) * 16;
            int gr = row0 + ar;
            av = make_float4(0.f, 0.f, 0.f, 0.f);
            if (gr < n) av = *reinterpret_cast<const float4*>(A + (size_t)gr * K + k0 + aq * 4);
            #pragma unroll
            for (int p = 0; p < BL; ++p)
                bv[p] = *reinterpret_cast<const float4*>(W + (size_t)(k0 + bkr + p * RPP) * M + bcq * 4);
        }
        // compute on current buffer
        #pragma unroll
        for (int kk = 0; kk < 16; ++kk) {
            unsigned long long a2[2];
            #pragma unroll
            for (int i = 0; i < 2; ++i)
                a2[i] = *reinterpret_cast<const unsigned long long*>(&As[cb][kk][ty * 4 + 2 * i]);
            unsigned long long b2[TN];
            #pragma unroll
            for (int j4 = 0; j4 < TN; j4 += 4) {
                float4 bq = *reinterpret_cast<const float4*>(&Bs[cb][kk][tx * TN + j4]);
                PACK_F32X2(b2[j4 + 0], bq.x, bq.x);
                PACK_F32X2(b2[j4 + 1], bq.y, bq.y);
                PACK_F32X2(b2[j4 + 2], bq.z, bq.z);
                PACK_F32X2(b2[j4 + 3], bq.w, bq.w);
            }
            #pragma unroll
            for (int i = 0; i < 2; ++i)
                #pragma unroll
                for (int j = 0; j < TN; ++j)
                    FMA_F32X2(acc[i][j], a2[i], b2[j], acc[i][j]);
        }
        // stage prefetched tile into other buffer
        if (it < 7) {
            int nb = cb ^ 1;
            As[nb][aq * 4 + 0][ar] = av.x; As[nb][aq * 4 + 1][ar] = av.y;
            As[nb][aq * 4 + 2][ar] = av.z; As[nb][aq * 4 + 3][ar] = av.w;
            #pragma unroll
            for (int p = 0; p < BL; ++p)
                *reinterpret_cast<float4*>(&Bs[nb][bkr + p * RPP][bcq * 4]) = bv[p];
        }
        __syncthreads();
    }

    // ---- epilogue ----
    #pragma unroll
    for (int i = 0; i < 2; ++i) {
        int gr = row0 + ty * 4 + 2 * i;
        float lo[TN], hi[TN];
        #pragma unroll
        for (int j = 0; j < TN; ++j) UNPACK_F32X2(lo[j], hi[j], acc[i][j]);
        if (gr < n) {
            #pragma unroll
            for (int j = 0; j < TN; j += 4)
                *reinterpret_cast<float4*>(C + (size_t)gr * M + tx * TN + j) =
                    make_float4(lo[j], lo[j + 1], lo[j + 2], lo[j + 3]);
        }
        if (gr + 1 < n) {
            #pragma unroll
            for (int j = 0; j < TN; j += 4)
                *reinterpret_cast<float4*>(C + (size_t)(gr + 1) * M + tx * TN + j) =
                    make_float4(hi[j], hi[j + 1], hi[j + 2], hi[j + 3]);
        }
    }
}

// ---------------- fused attention, dual-state online softmax ----------------
// one warp per dst node; lane holds channels [lane*VPL, lane*VPL+VPL)
template <int F, int C, bool DOELU>
__global__ __launch_bounds__(256) void edge_kernel(
    const float* __restrict__ att, const float* __restrict__ bias,
    int out_ext, float* __restrict__ Cext, int n) {
    constexpr int VPL = F / 32;
    constexpr int GR  = C / VPL;      // lanes per head group
    float* out = out_ext ? Cext : g_h;
    int w    = (blockIdx.x * blockDim.x + threadIdx.x) >> 5;
    int lane = threadIdx.x & 31;
    if (w >= n) return;

    float xrv[VPL], av[VPL], bv[VPL];
    if (VPL == 4) {
        float4 t0 = *reinterpret_cast<const float4*>(g_xr + (size_t)w * F + lane * 4);
        xrv[0] = t0.x; xrv[1] = t0.y; xrv[2] = t0.z; xrv[3] = t0.w;
        float4 t1 = *reinterpret_cast<const float4*>(att + lane * 4);
        av[0] = t1.x; av[1] = t1.y; av[2] = t1.z; av[3] = t1.w;
        float4 t2 = *reinterpret_cast<const float4*>(bias + lane * 4);
        bv[0] = t2.x; bv[1] = t2.y; bv[2] = t2.z; bv[3] = t2.w;
    } else {
        float2 t0 = *reinterpret_cast<const float2*>(g_xr + (size_t)w * F + lane * 2);
        xrv[0] = t0.x; xrv[1] = t0.y;
        float2 t1 = *reinterpret_cast<const float2*>(att + lane * 2);
        av[0] = t1.x; av[1] = t1.y;
        float2 t2 = *reinterpret_cast<const float2*>(bias + lane * 2);
        bv[0] = t2.x; bv[1] = t2.y;
    }

    // two independent online-softmax states (even/odd edges)
    float mA = -INFINITY, sA = 0.f, mB = -INFINITY, sB = 0.f;
    float accA[VPL], accB[VPL];
    #pragma unroll
    for (int j = 0; j < VPL; ++j) { accA[j] = 0.f; accB[j] = 0.f; }

    int e0 = g_off[w], e1 = g_off[w + 1];
    int e = e0;
    for (; e + 1 < e1; e += 2) {
        int s0 = g_srcs[e], s1 = g_srcs[e + 1];
        float xv0[VPL], xv1[VPL];
        if (VPL == 4) {
            float4 u = *reinterpret_cast<const float4*>(g_xl + (size_t)s0 * F + lane * 4);
            xv0[0] = u.x; xv0[1] = u.y; xv0[2] = u.z; xv0[3] = u.w;
            float4 v = *reinterpret_cast<const float4*>(g_xl + (size_t)s1 * F + lane * 4);
            xv1[0] = v.x; xv1[1] = v.y; xv1[2] = v.z; xv1[3] = v.w;
        } else {
            float2 u = *reinterpret_cast<const float2*>(g_xl + (size_t)s0 * F + lane * 2);
            xv0[0] = u.x; xv0[1] = u.y;
            float2 v = *reinterpret_cast<const float2*>(g_xl + (size_t)s1 * F + lane * 2);
            xv1[0] = v.x; xv1[1] = v.y;
        }
        float p0 = 0.f, p1 = 0.f;
        #pragma unroll
        for (int j = 0; j < VPL; ++j) {
            float m0 = xv0[j] + xrv[j];
            float m1 = xv1[j] + xrv[j];
            p0 = fmaf(av[j], (m0 > 0.f) ? m0 : 0.2f * m0, p0);
            p1 = fmaf(av[j], (m1 > 0.f) ? m1 : 0.2f * m1, p1);
        }
        #pragma unroll
        for (int o = 1; o < GR; o <<= 1) {
            p0 += __shfl_xor_sync(0xffffffffu, p0, o);
            p1 += __shfl_xor_sync(0xffffffffu, p1, o);
        }
        // independent state updates (chains overlap)
        float nmA = fmaxf(mA, p0);
        float scA = __expf(mA - nmA);
        float wA  = __expf(p0 - nmA);
        float nmB = fmaxf(mB, p1);
        float scB = __expf(mB - nmB);
        float wB  = __expf(p1 - nmB);
        sA = sA * scA + wA;
        sB = sB * scB + wB;
        #pragma unroll
        for (int j = 0; j < VPL; ++j) {
            accA[j] = fmaf(accA[j], scA, wA * xv0[j]);
            accB[j] = fmaf(accB[j], scB, wB * xv1[j]);
        }
        mA = nmA; mB = nmB;
    }
    if (e < e1) {  // leftover edge -> state A
        int s0 = g_srcs[e];
        float xv0[VPL];
        if (VPL == 4) {
            float4 u = *reinterpret_cast<const float4*>(g_xl + (size_t)s0 * F + lane * 4);
            xv0[0] = u.x; xv0[1] = u.y; xv0[2] = u.z; xv0[3] = u.w;
        } else {
            float2 u = *reinterpret_cast<const float2*>(g_xl + (size_t)s0 * F + lane * 2);
            xv0[0] = u.x; xv0[1] = u.y;
        }
        float p0 = 0.f;
        #pragma unroll
        for (int j = 0; j < VPL; ++j) {
            float m0 = xv0[j] + xrv[j];
            p0 = fmaf(av[j], (m0 > 0.f) ? m0 : 0.2f * m0, p0);
        }
        #pragma unroll
        for (int o = 1; o < GR; o <<= 1) p0 += __shfl_xor_sync(0xffffffffu, p0, o);
        float nmA = fmaxf(mA, p0);
        float scA = __expf(mA - nmA);
        float wA  = __expf(p0 - nmA);
        sA = sA * scA + wA;
        #pragma unroll
        for (int j = 0; j < VPL; ++j) accA[j] = fmaf(accA[j], scA, wA * xv0[j]);
        mA = nmA;
    }
    // merge B into A  (deg>=1 guarantees mA > -inf)
    float m   = fmaxf(mA, mB);
    float cA  = __expf(mA - m);
    float cB  = (sB > 0.f) ? __expf(mB - m) : 0.f;
    float ssum = sA * cA + sB * cB;
    float inv = 1.f / ssum;
    float o_[VPL];
    #pragma unroll
    for (int j = 0; j < VPL; ++j) {
        float a = accA[j] * cA + accB[j] * cB;
        float v = fmaf(a, inv, bv[j]);
        if (DOELU) v = (v > 0.f) ? v : expm1f(v);
        o_[j] = v;
    }
    if (VPL == 4) {
        *reinterpret_cast<float4*>(out + (size_t)w * F + lane * 4) =
            make_float4(o_[0], o_[1], o_[2], o_[3]);
    } else {
        *reinterpret_cast<float2*>(out + (size_t)w * F + lane * 2) =
            make_float2(o_[0], o_[1]);
    }
}

// ---------------- launch (kernel launches ONLY) ----------------
extern "C" void kernel_launch(void* const* d_in, const int* in_sizes, int n_in,
                              void* d_out, int out_size) {
    const float* x   = (const float*)d_in[0];
    const int*   ei  = (const int*)d_in[1];
    const float* Wl1 = (const float*)d_in[2];
    const float* Wr1 = (const float*)d_in[3];
    const float* a1  = (const float*)d_in[4];
    const float* b1  = (const float*)d_in[5];
    const float* Wl2 = (const float*)d_in[6];
    const float* Wr2 = (const float*)d_in[7];
    const float* a2  = (const float*)d_in[8];
    const float* b2  = (const float*)d_in[9];
    const float* Wl3 = (const float*)d_in[10];
    const float* Wr3 = (const float*)d_in[11];
    const float* a3  = (const float*)d_in[12];
    const float* b3  = (const float*)d_in[13];
    float* out = (float*)d_out;

    int N = in_sizes[0] / 128;
    int E = in_sizes[1] / 2;

    dim3 gGemm(1, (N + 63) / 64, 2);
    int  eBlocks = (N + 7) / 8;

    // CSR + layer-1 GEMM interleaved (GEMM independent of CSR; puts GEMM in ncu slot)
    zero_kernel<<<(N + 255) / 256, 256>>>(N);
    hist_kernel<<<(E + 255) / 256, 256>>>(ei, E);
    scan_kernel<<<1, 1024>>>(N);
    sgemm3<128, 8><<<gGemm, 256>>>(x, 1, Wl1, Wr1, N, 128);       // layer 1 xl & xr
    scatter_kernel<<<(E + N + 255) / 256, 256>>>(ei, E, N);
    edge_kernel<128, 32, true><<<eBlocks, 256>>>(a1, b1, 0, nullptr, N);

    // layer 2
    sgemm3<128, 8><<<gGemm, 256>>>(nullptr, 0, Wl2, Wr2, N, 128);
    edge_kernel<128, 32, true><<<eBlocks, 256>>>(a2, b2, 0, nullptr, N);

    // layer 3: heads=1, mean over 1 head == identity, no ELU, write d_out
    sgemm3<64, 4><<<gGemm, 256>>>(nullptr, 0, Wl3, Wr3, N, 64);
    edge_kernel<64, 64, false><<<eBlocks, 256>>>(a3, b3, 1, out, N);
}